// round 15
// baseline (speedup 1.0000x reference)
#include <cuda_runtime.h>
#include <cuda_bf16.h>
#include <math.h>
#include <stdint.h>

// Laplace diagonal recurrence:
//   out[t, i, f] = e[i] * out[t-1, i, f] + decay[i] * inp[t, f]
// T = 2048, N_S = 108, F = 256, fp32.
//
// R15 = R13 (71.7us) + tightened per-ib warm-up table only
// ({8,8,8,16,16,24,32,40,56}, e^-9.5..e^-10 truncation margin) ->
// critical-path blocks 192->184 steps. The L2::evict_last input-load hint
// from R14 is dropped (ptxas requires v8.b32/v4.b64 widths for it; expected
// value <1%). Core (validated at the ~6300 B/cyc LTS-cap floor): 128 thr,
// KI=6 (GI=12, NIB=9), CHUNK=128, PF=8 register pipeline, f32x2 math,
// st.global.cs.v4 stores, grid 9x16 = 144 blocks (one wave).

constexpr int T_LEN  = 2048;
constexpr int F      = 256;
constexpr int NS     = 108;
constexpr int CHUNK  = 128;
constexpr int NCHUNK = T_LEN / CHUNK;   // 16
constexpr int KI     = 6;               // i-states per thread
constexpr int GI     = 12;              // i-values per block
constexpr int NIB    = NS / GI;         // 9
constexpr int PF     = 8;               // prefetch depth (rows)
constexpr int F4     = F / 4;           // 64 float4 lanes per row

// Per-ib warm-up rows: ceil(~9.5 / s_min(ib)) rounded to multiple of 8.
__device__ __constant__ int WTAB[NIB] = {8, 8, 8, 16, 16, 24, 32, 40, 56};

typedef unsigned long long u64;

__device__ __forceinline__ u64 fma2(u64 a, u64 b, u64 c) {
    u64 d;
    asm("fma.rn.f32x2 %0, %1, %2, %3;" : "=l"(d) : "l"(a), "l"(b), "l"(c));
    return d;
}
__device__ __forceinline__ u64 mul2(u64 a, u64 b) {
    u64 d;
    asm("mul.rn.f32x2 %0, %1, %2;" : "=l"(d) : "l"(a), "l"(b));
    return d;
}
__device__ __forceinline__ u64 pack2(float lo, float hi) {
    u64 d;
    asm("mov.b64 %0, {%1, %2};" : "=l"(d) : "f"(lo), "f"(hi));
    return d;
}
__device__ __forceinline__ void stcs4(float4* p, u64 lo, u64 hi) {
    asm volatile("st.global.cs.v4.b32 [%0], {%1, %2, %3, %4};"
                 :: "l"(p),
                    "r"((unsigned)(lo & 0xffffffffu)), "r"((unsigned)(lo >> 32)),
                    "r"((unsigned)(hi & 0xffffffffu)), "r"((unsigned)(hi >> 32))
                 : "memory");
}

union V4 {
    float4 f;
    u64    u[2];
};

__global__ __launch_bounds__(128, 1)
void laplace_kernel(const float* __restrict__ inp, float* __restrict__ out) {
    const int tid = threadIdx.x;
    const int fq  = tid & 63;        // float4 lane: f = 4*fq
    const int iq  = tid >> 6;        // 0..1 -> which half of the 12 i's
    const int ib  = blockIdx.x;      // 0..8
    const int chunk = blockIdx.y;    // 0..15

    // Per-i constants in double precision (matches reference ~1e-7).
    u64 e2[KI], d2[KI];
    const double c = pow(20.0, 1.0 / 99.0) - 1.0;
    #pragma unroll
    for (int k = 0; k < KI; k++) {
        int i = ib * GI + iq * KI + k;
        double tau = pow(1.0 + c, (double)(i - 4));
        double s   = 4.0 / tau;
        double ed  = exp(-s);
        float ef = (float)ed;
        float df = (float)((1.0 - ed) / s);
        e2[k] = pack2(ef, ef);
        d2[k] = pack2(df, df);
    }

    const int t_start = chunk * CHUNK;
    const int wneed   = WTAB[ib];                             // 8..56, mult of 8
    const int warm    = (t_start < wneed) ? t_start : wneed;  // 0 or wneed
    const int t0      = t_start - warm;
    const int steps   = warm + CHUNK;

    const float4* __restrict__ ip = reinterpret_cast<const float4*>(inp)
                                    + (size_t)t0 * F4 + fq;

    // Scaled states: st' = e*st' + x;  out = dcy * st'.
    u64 st[KI][2];
    #pragma unroll
    for (int k = 0; k < KI; k++) { st[k][0] = 0ull; st[k][1] = 0ull; }

    // Prime the register pipeline.
    V4 pf[PF];
    #pragma unroll
    for (int j = 0; j < PF; j++) pf[j].f = __ldg(ip + j * F4);

    // ---- warm-up (no stores); warm is 0 or a multiple of PF ----
    for (int tb = 0; tb < warm; tb += PF) {
        #pragma unroll
        for (int j = 0; j < PF; j++) {
            const int t  = tb + j;
            const u64 x0 = pf[j].u[0];
            const u64 x1 = pf[j].u[1];
            const int tn = t + PF;
            if (tn < steps) pf[j].f = __ldg(ip + (size_t)tn * F4);
            #pragma unroll
            for (int k = 0; k < KI; k++) {
                st[k][0] = fma2(e2[k], st[k][0], x0);
                st[k][1] = fma2(e2[k], st[k][1], x1);
            }
        }
    }

    // ---- main: CHUNK=128 stored rows, 6 STG.128.cs per thread per row ----
    float4* op = reinterpret_cast<float4*>(out)
               + ((size_t)t_start * NS + (size_t)(ib * GI + iq * KI)) * F4 + fq;
    for (int tb = 0; tb < CHUNK; tb += PF) {
        #pragma unroll
        for (int j = 0; j < PF; j++) {
            const int t  = warm + tb + j;
            const u64 x0 = pf[j].u[0];
            const u64 x1 = pf[j].u[1];
            const int tn = t + PF;
            if (tn < steps) pf[j].f = __ldg(ip + (size_t)tn * F4);
            #pragma unroll
            for (int k = 0; k < KI; k++) {
                st[k][0] = fma2(e2[k], st[k][0], x0);
                st[k][1] = fma2(e2[k], st[k][1], x1);
                u64 o0 = mul2(d2[k], st[k][0]);
                u64 o1 = mul2(d2[k], st[k][1]);
                stcs4(op + k * F4, o0, o1);
            }
            op += NS * F4;
        }
    }
}

extern "C" void kernel_launch(void* const* d_in, const int* in_sizes, int n_in,
                              void* d_out, int out_size) {
    const float* inp = (const float*)d_in[0];
    float* out       = (float*)d_out;
    dim3 grid(NIB, NCHUNK);   // 9 x 16 = 144 blocks
    laplace_kernel<<<grid, 128>>>(inp, out);
}

// round 16
// speedup vs baseline: 1.2081x; 1.2081x over previous
#include <cuda_runtime.h>
#include <cuda_bf16.h>
#include <math.h>
#include <stdint.h>

// Laplace diagonal recurrence:
//   out[t, i, f] = e[i] * out[t-1, i, f] + decay[i] * inp[t, f]
// T = 2048, N_S = 108, F = 256, fp32.
//
// R16 = R15 core at the LTS-cap floor, moved to 256-bit memory ops
// (sm_103a .v4.b64 global ld/st): halves store wavefront count and enables
// the legal ld.global.nc.L2::evict_last form for input residency.
// Layout: 128 thr; lane = tid&31 covers a full 1KB row in 32B pieces;
// iq = tid>>5 in 0..3 with KI=3 i-states of float8 => GI=12, NIB=9.
// CHUNK=128, per-ib warm table {8,8,8,16,16,24,32,40,56}, PF=8 register
// pipeline, f32x2 math, st.global.cs.v4.b64 stores, grid 9x16 = 144.

constexpr int T_LEN  = 2048;
constexpr int F      = 256;
constexpr int NS     = 108;
constexpr int CHUNK  = 128;
constexpr int NCHUNK = T_LEN / CHUNK;   // 16
constexpr int KI     = 3;               // i-states per thread (float8 each)
constexpr int GI     = 12;              // i-values per block
constexpr int NIB    = NS / GI;         // 9
constexpr int PF     = 8;               // prefetch depth (rows)
constexpr int ROWB   = F * 4;           // 1024 bytes per (t) row per i

__device__ __constant__ int WTAB[NIB] = {8, 8, 8, 16, 16, 24, 32, 40, 56};

typedef unsigned long long u64;

__device__ __forceinline__ u64 fma2(u64 a, u64 b, u64 c) {
    u64 d;
    asm("fma.rn.f32x2 %0, %1, %2, %3;" : "=l"(d) : "l"(a), "l"(b), "l"(c));
    return d;
}
__device__ __forceinline__ u64 mul2(u64 a, u64 b) {
    u64 d;
    asm("mul.rn.f32x2 %0, %1, %2;" : "=l"(d) : "l"(a), "l"(b));
    return d;
}
__device__ __forceinline__ u64 pack2(float lo, float hi) {
    u64 d;
    asm("mov.b64 %0, {%1, %2};" : "=l"(d) : "f"(lo), "f"(hi));
    return d;
}
// 256-bit input load, non-coherent, L2 evict-last (keep shared input hot).
__device__ __forceinline__ void ldg256_el(const void* p, u64* v) {
    asm volatile("ld.global.nc.L2::evict_last.v4.b64 {%0, %1, %2, %3}, [%4];"
                 : "=l"(v[0]), "=l"(v[1]), "=l"(v[2]), "=l"(v[3])
                 : "l"(p));
}
// 256-bit store, evict-first.
__device__ __forceinline__ void stg256_cs(void* p, const u64* v) {
    asm volatile("st.global.cs.v4.b64 [%0], {%1, %2, %3, %4};"
                 :: "l"(p), "l"(v[0]), "l"(v[1]), "l"(v[2]), "l"(v[3])
                 : "memory");
}

__global__ __launch_bounds__(128, 1)
void laplace_kernel(const float* __restrict__ inp, float* __restrict__ out) {
    const int tid  = threadIdx.x;
    const int lane = tid & 31;       // 32B piece within a 1KB row
    const int iq   = tid >> 5;       // 0..3 -> which triple of the 12 i's
    const int ib   = blockIdx.x;     // 0..8
    const int chunk = blockIdx.y;    // 0..15

    // Per-i constants in double precision (matches reference ~1e-7).
    u64 e2[KI], d2[KI];
    const double c = pow(20.0, 1.0 / 99.0) - 1.0;
    #pragma unroll
    for (int k = 0; k < KI; k++) {
        int i = ib * GI + iq * KI + k;
        double tau = pow(1.0 + c, (double)(i - 4));
        double s   = 4.0 / tau;
        double ed  = exp(-s);
        float ef = (float)ed;
        float df = (float)((1.0 - ed) / s);
        e2[k] = pack2(ef, ef);
        d2[k] = pack2(df, df);
    }

    const int t_start = chunk * CHUNK;
    const int wneed   = WTAB[ib];                             // 8..56, mult of 8
    const int warm    = (t_start < wneed) ? t_start : wneed;  // 0 or wneed
    const int t0      = t_start - warm;
    const int steps   = warm + CHUNK;

    const char* __restrict__ ipb = reinterpret_cast<const char*>(inp)
                                   + (size_t)t0 * ROWB + lane * 32;

    // Scaled states: st' = e*st' + x;  out = dcy * st'.  float8 per state.
    u64 st[KI][4];
    #pragma unroll
    for (int k = 0; k < KI; k++)
        #pragma unroll
        for (int q = 0; q < 4; q++) st[k][q] = 0ull;

    // Prime the register pipeline (PF rows of 32B each).
    u64 pf[PF][4];
    #pragma unroll
    for (int j = 0; j < PF; j++) ldg256_el(ipb + (size_t)j * ROWB, pf[j]);

    // ---- warm-up (no stores); warm is 0 or a multiple of PF ----
    for (int tb = 0; tb < warm; tb += PF) {
        #pragma unroll
        for (int j = 0; j < PF; j++) {
            const int t = tb + j;
            u64 x[4];
            #pragma unroll
            for (int q = 0; q < 4; q++) x[q] = pf[j][q];
            const int tn = t + PF;
            if (tn < steps) ldg256_el(ipb + (size_t)tn * ROWB, pf[j]);
            #pragma unroll
            for (int k = 0; k < KI; k++)
                #pragma unroll
                for (int q = 0; q < 4; q++)
                    st[k][q] = fma2(e2[k], st[k][q], x[q]);
        }
    }

    // ---- main: CHUNK=128 stored rows, 3 STG.256.cs per thread per row ----
    char* opb = reinterpret_cast<char*>(out)
              + ((size_t)t_start * NS + (size_t)(ib * GI + iq * KI)) * ROWB
              + lane * 32;
    for (int tb = 0; tb < CHUNK; tb += PF) {
        #pragma unroll
        for (int j = 0; j < PF; j++) {
            const int t = warm + tb + j;
            u64 x[4];
            #pragma unroll
            for (int q = 0; q < 4; q++) x[q] = pf[j][q];
            const int tn = t + PF;
            if (tn < steps) ldg256_el(ipb + (size_t)tn * ROWB, pf[j]);
            #pragma unroll
            for (int k = 0; k < KI; k++) {
                u64 o[4];
                #pragma unroll
                for (int q = 0; q < 4; q++) {
                    st[k][q] = fma2(e2[k], st[k][q], x[q]);
                    o[q]     = mul2(d2[k], st[k][q]);
                }
                stg256_cs(opb + (size_t)k * ROWB, o);
            }
            opb += (size_t)NS * ROWB;
        }
    }
}

extern "C" void kernel_launch(void* const* d_in, const int* in_sizes, int n_in,
                              void* d_out, int out_size) {
    const float* inp = (const float*)d_in[0];
    float* out       = (float*)d_out;
    dim3 grid(NIB, NCHUNK);   // 9 x 16 = 144 blocks
    laplace_kernel<<<grid, 128>>>(inp, out);
}